// round 14
// baseline (speedup 1.0000x reference)
#include <cuda_runtime.h>
#include <cuda_fp16.h>
#include <math.h>

#define HIDDEN 128
#define MAXN 50000
#define MAXE 800000

// ---------------- scratch (device globals: no allocation allowed) ----------
__device__ __half g_zt[(size_t)MAXN * HIDDEN];  // z~ = x@M2^T + c; then scaled by dinv
__device__ int    g_degi[MAXN];                 // in-degree (int)
__device__ float  g_dinv[MAXN];                 // deg^-1/2
__device__ int    g_off[MAXN];                  // CSR starts; after fill = ends
__device__ int    g_edge[MAXE];                 // src per CSR slot (4B)
__device__ float  g_M2[HIDDEN * HIDDEN];        // M2 = W @ W (fp32)
__device__ float  g_c[HIDDEN];                  // c  = W @ b
__device__ int    g_bsum[64];                   // block sums for scan

// ---------------- degree (int) ----------------------------------------------
__global__ void deg_kernel(const int* __restrict__ dst, int e) {
    int i = blockIdx.x * blockDim.x + threadIdx.x;
    if (i < e) atomicAdd(&g_degi[dst[i]], 1);
}

// ---------------- 2-kernel scan -> exclusive starts (+ fused deg^-1/2) -------
__global__ void __launch_bounds__(1024)
scan_block_kernel(int n) {
    __shared__ int sh[1024];
    int t = threadIdx.x;
    int i = blockIdx.x * 1024 + t;
    int v = (i < n) ? g_degi[i] : 0;
    if (i < n) g_dinv[i] = rsqrtf((float)v);
    sh[t] = v;
    __syncthreads();
    for (int d = 1; d < 1024; d <<= 1) {
        int u = (t >= d) ? sh[t - d] : 0;
        __syncthreads();
        sh[t] += u;
        __syncthreads();
    }
    if (i < n) g_off[i] = sh[t] - v;           // exclusive within block
    if (t == 1023) g_bsum[blockIdx.x] = sh[1023];
}

__global__ void __launch_bounds__(1024)
scan_add_kernel(int n) {
    __shared__ int pre;
    int blk = blockIdx.x;
    if (threadIdx.x == 0) {
        int s = 0;
        for (int i = 0; i < blk; i++) s += g_bsum[i];
        pre = s;
    }
    __syncthreads();
    int i = blk * 1024 + threadIdx.x;
    if (i < n && blk > 0) g_off[i] += pre;
}

// ---------------- CSR fill: cursor-free, 4B record (src only) ---------------
__global__ void fill_kernel(const int* __restrict__ src, const int* __restrict__ dst, int e) {
    int i = blockIdx.x * blockDim.x + threadIdx.x;
    if (i < e) {
        int s = src[i];
        int d = dst[i];
        int pos = atomicAdd(&g_off[d], 1);
        g_edge[pos] = s;
    }
}

// ---------------- M2 = W @ W and c = W @ b (tiny, side stream, t=0) ----------
__global__ void __launch_bounds__(256)
mat_kernel(const float* __restrict__ W, const float* __restrict__ b) {
    if (blockIdx.x == 16) {
        int j = threadIdx.x;
        if (j < HIDDEN) {
            float acc = 0.f;
            for (int k = 0; k < HIDDEN; k++) acc += W[j * HIDDEN + k] * b[k];
            g_c[j] = acc;
        }
        return;
    }
    __shared__ float Wsh[8][HIDDEN];
    const int jbase = blockIdx.x * 8;
    const int tid = threadIdx.x;
    for (int i = tid; i < 8 * HIDDEN; i += 256)
        Wsh[i >> 7][i & 127] = W[(jbase + (i >> 7)) * HIDDEN + (i & 127)];
    __syncthreads();
    const int m = tid & 127;
    const int half = tid >> 7;
    float acc[4] = {0.f, 0.f, 0.f, 0.f};
    for (int k = 0; k < HIDDEN; k++) {
        float wk = __ldg(&W[k * HIDDEN + m]);
#pragma unroll
        for (int q = 0; q < 4; q++) acc[q] += Wsh[half * 4 + q][k] * wk;
    }
#pragma unroll
    for (int q = 0; q < 4; q++)
        g_M2[(jbase + half * 4 + q) * HIDDEN + m] = acc[q];
}

// ---------------- packed f32x2 helpers ---------------------------------------
__device__ __forceinline__ unsigned long long f32x2_pack(float lo, float hi) {
    unsigned long long r;
    asm("mov.b64 %0, {%1, %2};" : "=l"(r) : "f"(lo), "f"(hi));
    return r;
}
__device__ __forceinline__ void f32x2_fma(unsigned long long& d,
                                          unsigned long long a, unsigned long long b) {
    asm("fma.rn.f32x2 %0, %1, %2, %0;" : "+l"(d) : "l"(a), "l"(b));
}
__device__ __forceinline__ float2 f32x2_unpack(unsigned long long v) {
    float2 r;
    asm("mov.b64 {%0, %1}, %2;" : "=f"(r.x), "=f"(r.y) : "l"(v));
    return r;
}

__device__ __forceinline__ float gelu_exact(float v) {
    return 0.5f * v * (1.0f + erff(v * 0.70710678118654752f));
}

// ---------------- GEMM (side stream, t=0): z~ = x @ M2^T + c, fp16 out -------
// No dinv dependency -> fully concurrent with CSR chain.
#define GEMM_ROWS 64
#define WT_STRIDE 132
#define AT_STRIDE 66

__global__ void __launch_bounds__(256, 2)
gemmz_kernel(const float* __restrict__ A, const float* __restrict__ M2,
             const float* __restrict__ cvec, int n) {
    extern __shared__ float smem[];
    float* Wt = smem;                          // [k][j], stride 132
    float* At = smem + HIDDEN * WT_STRIDE;     // [k][r], stride 66

    const int tid  = threadIdx.x;
    const int row0 = blockIdx.x * GEMM_ROWS;

    for (int i = tid; i < HIDDEN * HIDDEN; i += 256) {
        int j = i >> 7;
        int k = i & 127;
        Wt[k * WT_STRIDE + j] = M2[i];
    }
    const float4* A4 = reinterpret_cast<const float4*>(A);
    for (int i = tid; i < GEMM_ROWS * 32; i += 256) {
        int r  = i >> 5;
        int c4 = i & 31;
        int gr = row0 + r;
        float4 v = (gr < n) ? A4[(size_t)gr * 32 + c4] : make_float4(0.f, 0.f, 0.f, 0.f);
        At[(4 * c4 + 0) * AT_STRIDE + r] = v.x;
        At[(4 * c4 + 1) * AT_STRIDE + r] = v.y;
        At[(4 * c4 + 2) * AT_STRIDE + r] = v.z;
        At[(4 * c4 + 3) * AT_STRIDE + r] = v.w;
    }
    __syncthreads();

    const int tx = tid & 31;
    const int ty = tid >> 5;

    unsigned long long acc[4][4];
#pragma unroll
    for (int p = 0; p < 4; p++)
#pragma unroll
        for (int c = 0; c < 4; c++) acc[p][c] = 0ull;

    const float* at_base = &At[ty * 8];
    const float* wt_base = &Wt[tx * 4];

#pragma unroll 4
    for (int k = 0; k < HIDDEN; k++) {
        float4 w = *reinterpret_cast<const float4*>(&wt_base[k * WT_STRIDE]);
        unsigned long long w0 = f32x2_pack(w.x, w.x);
        unsigned long long w1 = f32x2_pack(w.y, w.y);
        unsigned long long w2 = f32x2_pack(w.z, w.z);
        unsigned long long w3 = f32x2_pack(w.w, w.w);
        const float* ak = &at_base[k * AT_STRIDE];
        unsigned long long a0 = *reinterpret_cast<const unsigned long long*>(ak + 0);
        unsigned long long a1 = *reinterpret_cast<const unsigned long long*>(ak + 2);
        unsigned long long a2 = *reinterpret_cast<const unsigned long long*>(ak + 4);
        unsigned long long a3 = *reinterpret_cast<const unsigned long long*>(ak + 6);
        f32x2_fma(acc[0][0], a0, w0); f32x2_fma(acc[0][1], a0, w1);
        f32x2_fma(acc[0][2], a0, w2); f32x2_fma(acc[0][3], a0, w3);
        f32x2_fma(acc[1][0], a1, w0); f32x2_fma(acc[1][1], a1, w1);
        f32x2_fma(acc[1][2], a1, w2); f32x2_fma(acc[1][3], a1, w3);
        f32x2_fma(acc[2][0], a2, w0); f32x2_fma(acc[2][1], a2, w1);
        f32x2_fma(acc[2][2], a2, w2); f32x2_fma(acc[2][3], a2, w3);
        f32x2_fma(acc[3][0], a3, w0); f32x2_fma(acc[3][1], a3, w1);
        f32x2_fma(acc[3][2], a3, w2); f32x2_fma(acc[3][3], a3, w3);
    }

    float4 cv = reinterpret_cast<const float4*>(cvec)[tx];
    uint2* zt2 = reinterpret_cast<uint2*>(g_zt);
#pragma unroll
    for (int p = 0; p < 4; p++) {
        int r0 = row0 + ty * 8 + 2 * p;
        float2 c0 = f32x2_unpack(acc[p][0]);
        float2 c1 = f32x2_unpack(acc[p][1]);
        float2 c2 = f32x2_unpack(acc[p][2]);
        float2 c3 = f32x2_unpack(acc[p][3]);
        if (r0 < n) {
            __half2 h01 = __floats2half2_rn(c0.x + cv.x, c1.x + cv.y);
            __half2 h23 = __floats2half2_rn(c2.x + cv.z, c3.x + cv.w);
            uint2 u;
            u.x = *reinterpret_cast<unsigned*>(&h01);
            u.y = *reinterpret_cast<unsigned*>(&h23);
            zt2[(size_t)r0 * 32 + tx] = u;
        }
        if (r0 + 1 < n) {
            __half2 h01 = __floats2half2_rn(c0.y + cv.x, c1.y + cv.y);
            __half2 h23 = __floats2half2_rn(c2.y + cv.z, c3.y + cv.w);
            uint2 u;
            u.x = *reinterpret_cast<unsigned*>(&h01);
            u.y = *reinterpret_cast<unsigned*>(&h23);
            zt2[(size_t)(r0 + 1) * 32 + tx] = u;
        }
    }
}

// ---------------- scale: z~ *= dinv (in-place, replay-safe) ------------------
// Runs on side stream after gemmz + scan; overlaps fill on main stream.
__global__ void __launch_bounds__(256)
scale_kernel(int n) {
    int idx = blockIdx.x * 256 + threadIdx.x;     // one uint2 (4 halves) per thread
    if (idx >= n * 32) return;
    int row = idx >> 5;
    __half2 d2 = __float2half2_rn(__ldg(&g_dinv[row]));   // warp-uniform
    uint2* zt2 = reinterpret_cast<uint2*>(g_zt);
    uint2 u = zt2[idx];
    __half2 a = __hmul2(*reinterpret_cast<__half2*>(&u.x), d2);
    __half2 b = __hmul2(*reinterpret_cast<__half2*>(&u.y), d2);
    u.x = *reinterpret_cast<unsigned*>(&a);
    u.y = *reinterpret_cast<unsigned*>(&b);
    zt2[idx] = u;
}

// ---------------- final: out[i] = gelu(dinv_i * sum_e z'[s] + b) -------------
// Pure sum; 4-edge fp16 pairwise tree (6 HADD2) then one fp32 accumulate.
__global__ void __launch_bounds__(256)
gather_out_kernel(const float* __restrict__ bvec, float* __restrict__ out, int n) {
    int warp = (blockIdx.x * 256 + threadIdx.x) >> 5;
    int lane = threadIdx.x & 31;
    if (warp >= n) return;
    int p  = (warp == 0) ? 0 : __ldg(&g_off[warp - 1]);
    int pe = __ldg(&g_off[warp]);
    const uint2* z2 = reinterpret_cast<const uint2*>(g_zt);
    float4 acc = make_float4(0.f, 0.f, 0.f, 0.f);
#pragma unroll 1
    for (; p + 3 < pe; p += 4) {
        int s0 = __ldg(&g_edge[p]);
        int s1 = __ldg(&g_edge[p + 1]);
        int s2 = __ldg(&g_edge[p + 2]);
        int s3 = __ldg(&g_edge[p + 3]);
        uint2 u0 = __ldg(&z2[(size_t)s0 * 32 + lane]);
        uint2 u1 = __ldg(&z2[(size_t)s1 * 32 + lane]);
        uint2 u2 = __ldg(&z2[(size_t)s2 * 32 + lane]);
        uint2 u3 = __ldg(&z2[(size_t)s3 * 32 + lane]);
        __half2 px = __hadd2(__hadd2(*reinterpret_cast<__half2*>(&u0.x),
                                     *reinterpret_cast<__half2*>(&u1.x)),
                             __hadd2(*reinterpret_cast<__half2*>(&u2.x),
                                     *reinterpret_cast<__half2*>(&u3.x)));
        __half2 py = __hadd2(__hadd2(*reinterpret_cast<__half2*>(&u0.y),
                                     *reinterpret_cast<__half2*>(&u1.y)),
                             __hadd2(*reinterpret_cast<__half2*>(&u2.y),
                                     *reinterpret_cast<__half2*>(&u3.y)));
        float2 fx = __half22float2(px);
        float2 fy = __half22float2(py);
        acc.x += fx.x; acc.y += fx.y;
        acc.z += fy.x; acc.w += fy.y;
    }
    for (; p < pe; p++) {
        int s0 = __ldg(&g_edge[p]);
        uint2 u0 = __ldg(&z2[(size_t)s0 * 32 + lane]);
        float2 a0 = __half22float2(*reinterpret_cast<__half2*>(&u0.x));
        float2 b0 = __half22float2(*reinterpret_cast<__half2*>(&u0.y));
        acc.x += a0.x; acc.y += a0.y;
        acc.z += b0.x; acc.w += b0.y;
    }
    float di = __ldg(&g_dinv[warp]);
    float4 bv = reinterpret_cast<const float4*>(bvec)[lane];
    float4 o;
    o.x = gelu_exact(di * acc.x + bv.x);
    o.y = gelu_exact(di * acc.y + bv.y);
    o.z = gelu_exact(di * acc.z + bv.z);
    o.w = gelu_exact(di * acc.w + bv.w);
    reinterpret_cast<float4*>(out)[(size_t)warp * 32 + lane] = o;
}

// ---------------- launch -----------------------------------------------------
extern "C" void kernel_launch(void* const* d_in, const int* in_sizes, int n_in,
                              void* d_out, int out_size) {
    const float* x = (const float*)d_in[0];
    const float* W = (const float*)d_in[1];
    const float* b = (const float*)d_in[2];
    const int* ei  = (const int*)d_in[3];

    const int n = in_sizes[0] / HIDDEN;   // 50000
    const int e = in_sizes[3] / 2;        // 800000
    const int* src = ei;
    const int* dst = ei + e;

    float* out = (float*)d_out;

    static float* p_M2  = nullptr;
    static float* p_c   = nullptr;
    static int*   p_deg = nullptr;
    static cudaStream_t s2 = nullptr;
    static cudaEvent_t ev_fork = nullptr, ev_scan = nullptr, ev_join = nullptr;
    if (!p_M2) {
        cudaGetSymbolAddress((void**)&p_M2, g_M2);
        cudaGetSymbolAddress((void**)&p_c, g_c);
        cudaGetSymbolAddress((void**)&p_deg, g_degi);
        cudaStreamCreateWithFlags(&s2, cudaStreamNonBlocking);
        cudaEventCreateWithFlags(&ev_fork, cudaEventDisableTiming);
        cudaEventCreateWithFlags(&ev_scan, cudaEventDisableTiming);
        cudaEventCreateWithFlags(&ev_join, cudaEventDisableTiming);
        const size_t smem_bytes = (HIDDEN * WT_STRIDE + HIDDEN * AT_STRIDE) * sizeof(float);
        cudaFuncSetAttribute(gemmz_kernel,
                             cudaFuncAttributeMaxDynamicSharedMemorySize, (int)smem_bytes);
    }
    const size_t smem_bytes = (HIDDEN * WT_STRIDE + HIDDEN * AT_STRIDE) * sizeof(float);

    // ---- side stream: mat -> gemmz from t=0 (input-only deps) ---------------
    cudaEventRecord(ev_fork, 0);
    cudaStreamWaitEvent(s2, ev_fork, 0);
    mat_kernel<<<17, 256, 0, s2>>>(W, b);
    const int gemm_blocks = (n + GEMM_ROWS - 1) / GEMM_ROWS;
    gemmz_kernel<<<gemm_blocks, 256, smem_bytes, s2>>>(x, p_M2, p_c, n);

    // ---- main stream: CSR chain ---------------------------------------------
    cudaMemsetAsync(p_deg, 0, (size_t)n * sizeof(int));
    deg_kernel<<<(e + 255) / 256, 256>>>(dst, e);
    int nscan = (n + 1023) / 1024;  // 49
    scan_block_kernel<<<nscan, 1024>>>(n);
    scan_add_kernel<<<nscan, 1024>>>(n);
    cudaEventRecord(ev_scan, 0);

    // ---- side stream: scale z~ by dinv (after gemmz + scan); overlaps fill --
    cudaStreamWaitEvent(s2, ev_scan, 0);
    scale_kernel<<<(n * 32 + 255) / 256, 256, 0, s2>>>(n);
    cudaEventRecord(ev_join, s2);

    // ---- main stream: fill (concurrent with gemmz/scale), join, gather ------
    fill_kernel<<<(e + 255) / 256, 256>>>(src, dst, e);
    cudaStreamWaitEvent(0, ev_join, 0);
    unsigned gthreads = (unsigned)n * 32u;
    gather_out_kernel<<<(gthreads + 255) / 256, 256>>>(b, out, n);
}

// round 16
// speedup vs baseline: 1.0648x; 1.0648x over previous
#include <cuda_runtime.h>
#include <cuda_fp16.h>
#include <math.h>

#define HIDDEN 128
#define MAXN 50000
#define MAXE 800000

// ---------------- scratch (device globals: no allocation allowed) ----------
__device__ __half g_zt[(size_t)MAXN * HIDDEN];  // z' = dinv_s * (x@M2^T + c)  (fp16)
__device__ int    g_degi[MAXN];                 // in-degree; consumed+zeroed by offs
__device__ float  g_dinv[MAXN];                 // deg^-1/2
__device__ int    g_off[MAXN];                  // row cursor: start -> (after fill) end
__device__ int    g_start[MAXN];                // immutable row start
__device__ int    g_edge[MAXE];                 // src per CSR slot (4B)
__device__ float  g_M2[HIDDEN * HIDDEN];        // M2 = W @ W (fp32)
__device__ float  g_c[HIDDEN];                  // c  = W @ b
__device__ int    g_total;                      // range allocator; re-zeroed by deg

// ---------------- degree (also re-zeroes range allocator) --------------------
__global__ void deg_kernel(const int* __restrict__ dst, int e) {
    if (blockIdx.x == 0 && threadIdx.x == 0) g_total = 0;
    int i = blockIdx.x * blockDim.x + threadIdx.x;
    if (i < e) atomicAdd(&g_degi[dst[i]], 1);
}

// ---------------- offs: unordered range assignment (1 kernel, no memset) -----
// Each block shfl-scans its 1024 degrees, grabs a contiguous base via ONE
// atomicAdd. Ranges are unique+contiguous per row; global order is arbitrary,
// so the start is stored EXPLICITLY in g_start (gather must not derive it
// from the neighboring row). Also computes dinv and consumes+zeroes g_degi.
__global__ void __launch_bounds__(1024)
offs_kernel(int n) {
    __shared__ int warp_sums[32];
    __shared__ int block_base;
    const int t = threadIdx.x;
    const int i = blockIdx.x * 1024 + t;
    const int lane = t & 31;
    const int wid  = t >> 5;

    int v = 0;
    if (i < n) {
        v = g_degi[i];
        g_dinv[i] = rsqrtf((float)v);
        g_degi[i] = 0;                         // restore invariant for next replay
    }
    // warp inclusive scan
    int s = v;
#pragma unroll
    for (int d = 1; d < 32; d <<= 1) {
        int u = __shfl_up_sync(0xffffffffu, s, d);
        if (lane >= d) s += u;
    }
    if (lane == 31) warp_sums[wid] = s;
    __syncthreads();
    if (wid == 0) {
        int ws = warp_sums[lane];
#pragma unroll
        for (int d = 1; d < 32; d <<= 1) {
            int u = __shfl_up_sync(0xffffffffu, ws, d);
            if (lane >= d) ws += u;
        }
        warp_sums[lane] = ws;                  // inclusive warp prefix
        if (lane == 31) block_base = atomicAdd(&g_total, ws);
    }
    __syncthreads();
    if (i < n) {
        int start = block_base + (wid > 0 ? warp_sums[wid - 1] : 0) + s - v;
        g_off[i]   = start;                    // fill mutates this into the end
        g_start[i] = start;                    // immutable
    }
}

// ---------------- CSR fill: cursor-free, 4B record (src only) ---------------
__global__ void fill_kernel(const int* __restrict__ src, const int* __restrict__ dst, int e) {
    int i = blockIdx.x * blockDim.x + threadIdx.x;
    if (i < e) {
        int s = src[i];
        int d = dst[i];
        int pos = atomicAdd(&g_off[d], 1);
        g_edge[pos] = s;
    }
}

// ---------------- M2 = W @ W and c = W @ b (tiny, side stream, t=0) ----------
__global__ void __launch_bounds__(256)
mat_kernel(const float* __restrict__ W, const float* __restrict__ b) {
    if (blockIdx.x == 16) {
        int j = threadIdx.x;
        if (j < HIDDEN) {
            float acc = 0.f;
            for (int k = 0; k < HIDDEN; k++) acc += W[j * HIDDEN + k] * b[k];
            g_c[j] = acc;
        }
        return;
    }
    __shared__ float Wsh[8][HIDDEN];
    const int jbase = blockIdx.x * 8;
    const int tid = threadIdx.x;
    for (int i = tid; i < 8 * HIDDEN; i += 256)
        Wsh[i >> 7][i & 127] = W[(jbase + (i >> 7)) * HIDDEN + (i & 127)];
    __syncthreads();
    const int m = tid & 127;
    const int half = tid >> 7;
    float acc[4] = {0.f, 0.f, 0.f, 0.f};
    for (int k = 0; k < HIDDEN; k++) {
        float wk = __ldg(&W[k * HIDDEN + m]);
#pragma unroll
        for (int q = 0; q < 4; q++) acc[q] += Wsh[half * 4 + q][k] * wk;
    }
#pragma unroll
    for (int q = 0; q < 4; q++)
        g_M2[(jbase + half * 4 + q) * HIDDEN + m] = acc[q];
}

// ---------------- packed f32x2 helpers ---------------------------------------
__device__ __forceinline__ unsigned long long f32x2_pack(float lo, float hi) {
    unsigned long long r;
    asm("mov.b64 %0, {%1, %2};" : "=l"(r) : "f"(lo), "f"(hi));
    return r;
}
__device__ __forceinline__ void f32x2_fma(unsigned long long& d,
                                          unsigned long long a, unsigned long long b) {
    asm("fma.rn.f32x2 %0, %1, %2, %0;" : "+l"(d) : "l"(a), "l"(b));
}
__device__ __forceinline__ float2 f32x2_unpack(unsigned long long v) {
    float2 r;
    asm("mov.b64 {%0, %1}, %2;" : "=f"(r.x), "=f"(r.y) : "l"(v));
    return r;
}

__device__ __forceinline__ float gelu_exact(float v) {
    return 0.5f * v * (1.0f + erff(v * 0.70710678118654752f));
}

// ---------------- GEMM: z' = dinv * (x @ M2^T + c), fp16 out -----------------
// Runs after offs (needs dinv). FFMA2 at fp32 roofline.
#define GEMM_ROWS 64
#define WT_STRIDE 132
#define AT_STRIDE 66

__global__ void __launch_bounds__(256, 2)
gemmz_kernel(const float* __restrict__ A, const float* __restrict__ M2,
             const float* __restrict__ cvec, int n) {
    extern __shared__ float smem[];
    float* Wt = smem;                          // [k][j], stride 132
    float* At = smem + HIDDEN * WT_STRIDE;     // [k][r], stride 66

    const int tid  = threadIdx.x;
    const int row0 = blockIdx.x * GEMM_ROWS;

    for (int i = tid; i < HIDDEN * HIDDEN; i += 256) {
        int j = i >> 7;
        int k = i & 127;
        Wt[k * WT_STRIDE + j] = M2[i];
    }
    const float4* A4 = reinterpret_cast<const float4*>(A);
    for (int i = tid; i < GEMM_ROWS * 32; i += 256) {
        int r  = i >> 5;
        int c4 = i & 31;
        int gr = row0 + r;
        float4 v = (gr < n) ? A4[(size_t)gr * 32 + c4] : make_float4(0.f, 0.f, 0.f, 0.f);
        At[(4 * c4 + 0) * AT_STRIDE + r] = v.x;
        At[(4 * c4 + 1) * AT_STRIDE + r] = v.y;
        At[(4 * c4 + 2) * AT_STRIDE + r] = v.z;
        At[(4 * c4 + 3) * AT_STRIDE + r] = v.w;
    }
    __syncthreads();

    const int tx = tid & 31;
    const int ty = tid >> 5;

    unsigned long long acc[4][4];
#pragma unroll
    for (int p = 0; p < 4; p++)
#pragma unroll
        for (int c = 0; c < 4; c++) acc[p][c] = 0ull;

    const float* at_base = &At[ty * 8];
    const float* wt_base = &Wt[tx * 4];

#pragma unroll 4
    for (int k = 0; k < HIDDEN; k++) {
        float4 w = *reinterpret_cast<const float4*>(&wt_base[k * WT_STRIDE]);
        unsigned long long w0 = f32x2_pack(w.x, w.x);
        unsigned long long w1 = f32x2_pack(w.y, w.y);
        unsigned long long w2 = f32x2_pack(w.z, w.z);
        unsigned long long w3 = f32x2_pack(w.w, w.w);
        const float* ak = &at_base[k * AT_STRIDE];
        unsigned long long a0 = *reinterpret_cast<const unsigned long long*>(ak + 0);
        unsigned long long a1 = *reinterpret_cast<const unsigned long long*>(ak + 2);
        unsigned long long a2 = *reinterpret_cast<const unsigned long long*>(ak + 4);
        unsigned long long a3 = *reinterpret_cast<const unsigned long long*>(ak + 6);
        f32x2_fma(acc[0][0], a0, w0); f32x2_fma(acc[0][1], a0, w1);
        f32x2_fma(acc[0][2], a0, w2); f32x2_fma(acc[0][3], a0, w3);
        f32x2_fma(acc[1][0], a1, w0); f32x2_fma(acc[1][1], a1, w1);
        f32x2_fma(acc[1][2], a1, w2); f32x2_fma(acc[1][3], a1, w3);
        f32x2_fma(acc[2][0], a2, w0); f32x2_fma(acc[2][1], a2, w1);
        f32x2_fma(acc[2][2], a2, w2); f32x2_fma(acc[2][3], a2, w3);
        f32x2_fma(acc[3][0], a3, w0); f32x2_fma(acc[3][1], a3, w1);
        f32x2_fma(acc[3][2], a3, w2); f32x2_fma(acc[3][3], a3, w3);
    }

    float4 cv = reinterpret_cast<const float4*>(cvec)[tx];
    uint2* zt2 = reinterpret_cast<uint2*>(g_zt);
#pragma unroll
    for (int p = 0; p < 4; p++) {
        int r0 = row0 + ty * 8 + 2 * p;
        float2 c0 = f32x2_unpack(acc[p][0]);
        float2 c1 = f32x2_unpack(acc[p][1]);
        float2 c2 = f32x2_unpack(acc[p][2]);
        float2 c3 = f32x2_unpack(acc[p][3]);
        if (r0 < n) {
            float d0 = __ldg(&g_dinv[r0]);
            __half2 h01 = __floats2half2_rn(d0 * (c0.x + cv.x), d0 * (c1.x + cv.y));
            __half2 h23 = __floats2half2_rn(d0 * (c2.x + cv.z), d0 * (c3.x + cv.w));
            uint2 u;
            u.x = *reinterpret_cast<unsigned*>(&h01);
            u.y = *reinterpret_cast<unsigned*>(&h23);
            zt2[(size_t)r0 * 32 + tx] = u;
        }
        if (r0 + 1 < n) {
            float d1 = __ldg(&g_dinv[r0 + 1]);
            __half2 h01 = __floats2half2_rn(d1 * (c0.y + cv.x), d1 * (c1.y + cv.y));
            __half2 h23 = __floats2half2_rn(d1 * (c2.y + cv.z), d1 * (c3.y + cv.w));
            uint2 u;
            u.x = *reinterpret_cast<unsigned*>(&h01);
            u.y = *reinterpret_cast<unsigned*>(&h23);
            zt2[(size_t)(r0 + 1) * 32 + tx] = u;
        }
    }
}

// ---------------- final: out[i] = gelu(dinv_i * sum_e z'[s] + b) -------------
// Pure sum over [g_start[i], g_off[i]); 4-edge fp16 pairwise tree.
__global__ void __launch_bounds__(256)
gather_out_kernel(const float* __restrict__ bvec, float* __restrict__ out, int n) {
    int warp = (blockIdx.x * 256 + threadIdx.x) >> 5;
    int lane = threadIdx.x & 31;
    if (warp >= n) return;
    int p  = __ldg(&g_start[warp]);
    int pe = __ldg(&g_off[warp]);              // after fill = end of row
    const uint2* z2 = reinterpret_cast<const uint2*>(g_zt);
    float4 acc = make_float4(0.f, 0.f, 0.f, 0.f);
#pragma unroll 1
    for (; p + 3 < pe; p += 4) {
        int s0 = __ldg(&g_edge[p]);
        int s1 = __ldg(&g_edge[p + 1]);
        int s2 = __ldg(&g_edge[p + 2]);
        int s3 = __ldg(&g_edge[p + 3]);
        uint2 u0 = __ldg(&z2[(size_t)s0 * 32 + lane]);
        uint2 u1 = __ldg(&z2[(size_t)s1 * 32 + lane]);
        uint2 u2 = __ldg(&z2[(size_t)s2 * 32 + lane]);
        uint2 u3 = __ldg(&z2[(size_t)s3 * 32 + lane]);
        __half2 px = __hadd2(__hadd2(*reinterpret_cast<__half2*>(&u0.x),
                                     *reinterpret_cast<__half2*>(&u1.x)),
                             __hadd2(*reinterpret_cast<__half2*>(&u2.x),
                                     *reinterpret_cast<__half2*>(&u3.x)));
        __half2 py = __hadd2(__hadd2(*reinterpret_cast<__half2*>(&u0.y),
                                     *reinterpret_cast<__half2*>(&u1.y)),
                             __hadd2(*reinterpret_cast<__half2*>(&u2.y),
                                     *reinterpret_cast<__half2*>(&u3.y)));
        float2 fx = __half22float2(px);
        float2 fy = __half22float2(py);
        acc.x += fx.x; acc.y += fx.y;
        acc.z += fy.x; acc.w += fy.y;
    }
    for (; p < pe; p++) {
        int s0 = __ldg(&g_edge[p]);
        uint2 u0 = __ldg(&z2[(size_t)s0 * 32 + lane]);
        float2 a0 = __half22float2(*reinterpret_cast<__half2*>(&u0.x));
        float2 b0 = __half22float2(*reinterpret_cast<__half2*>(&u0.y));
        acc.x += a0.x; acc.y += a0.y;
        acc.z += b0.x; acc.w += b0.y;
    }
    float di = __ldg(&g_dinv[warp]);
    float4 bv = reinterpret_cast<const float4*>(bvec)[lane];
    float4 o;
    o.x = gelu_exact(di * acc.x + bv.x);
    o.y = gelu_exact(di * acc.y + bv.y);
    o.z = gelu_exact(di * acc.z + bv.z);
    o.w = gelu_exact(di * acc.w + bv.w);
    reinterpret_cast<float4*>(out)[(size_t)warp * 32 + lane] = o;
}

// ---------------- launch -----------------------------------------------------
extern "C" void kernel_launch(void* const* d_in, const int* in_sizes, int n_in,
                              void* d_out, int out_size) {
    const float* x = (const float*)d_in[0];
    const float* W = (const float*)d_in[1];
    const float* b = (const float*)d_in[2];
    const int* ei  = (const int*)d_in[3];

    const int n = in_sizes[0] / HIDDEN;   // 50000
    const int e = in_sizes[3] / 2;        // 800000
    const int* src = ei;
    const int* dst = ei + e;

    float* out = (float*)d_out;

    static float* p_M2 = nullptr;
    static float* p_c  = nullptr;
    static cudaStream_t s2 = nullptr;
    static cudaEvent_t ev_fork = nullptr, ev_offs = nullptr, ev_join = nullptr;
    if (!p_M2) {
        cudaGetSymbolAddress((void**)&p_M2, g_M2);
        cudaGetSymbolAddress((void**)&p_c, g_c);
        cudaStreamCreateWithFlags(&s2, cudaStreamNonBlocking);
        cudaEventCreateWithFlags(&ev_fork, cudaEventDisableTiming);
        cudaEventCreateWithFlags(&ev_offs, cudaEventDisableTiming);
        cudaEventCreateWithFlags(&ev_join, cudaEventDisableTiming);
        const size_t smem_bytes = (HIDDEN * WT_STRIDE + HIDDEN * AT_STRIDE) * sizeof(float);
        cudaFuncSetAttribute(gemmz_kernel,
                             cudaFuncAttributeMaxDynamicSharedMemorySize, (int)smem_bytes);
    }
    const size_t smem_bytes = (HIDDEN * WT_STRIDE + HIDDEN * AT_STRIDE) * sizeof(float);

    // ---- side stream: mat at t=0 (needs only W,b) ---------------------------
    cudaEventRecord(ev_fork, 0);
    cudaStreamWaitEvent(s2, ev_fork, 0);
    mat_kernel<<<17, 256, 0, s2>>>(W, b);

    // ---- main stream: deg -> offs (no memsets, single-kernel prefix) --------
    deg_kernel<<<(e + 255) / 256, 256>>>(dst, e);
    int nblk = (n + 1023) / 1024;  // 49
    offs_kernel<<<nblk, 1024>>>(n);
    cudaEventRecord(ev_offs, 0);

    // ---- side stream: gemmz after offs (needs dinv) + mat -------------------
    cudaStreamWaitEvent(s2, ev_offs, 0);
    const int gemm_blocks = (n + GEMM_ROWS - 1) / GEMM_ROWS;
    gemmz_kernel<<<gemm_blocks, 256, smem_bytes, s2>>>(x, p_M2, p_c, n);
    cudaEventRecord(ev_join, s2);

    // ---- main stream: fill (work-shares with gemmz), join, gather -----------
    fill_kernel<<<(e + 255) / 256, 256>>>(src, dst, e);
    cudaStreamWaitEvent(0, ev_join, 0);
    unsigned gthreads = (unsigned)n * 32u;
    gather_out_kernel<<<(gthreads + 255) / 256, 256>>>(b, out, n);
}